// round 9
// baseline (speedup 1.0000x reference)
#include <cuda_runtime.h>

#define NN 50000
#define DH 128
#define EMAX 600000

__device__ __align__(16) float g_h[(size_t)NN * DH];   // h = A @ W
__device__ __align__(16) float g_b[(size_t)NN * DH];   // layer-1 aggregate / relu'd layer-2 input
__device__ __align__(16) float g_deg[NN];
__device__ __align__(16) float g_dinv[NN];
__device__ __align__(16) float g_norm[EMAX];
__device__ __align__(16) int   g_src[EMAX];
__device__ __align__(16) int   g_dst[EMAX];
__device__ int g_is64;   // 1 if edge_index buffer is int64, 0 if int32

// ---------------- dtype probe ----------------
// If edge_index is int64 with node ids < 2^31, every odd 32-bit word is 0.
// If it is int32, odd words are random node ids — all-zero over 1024 samples
// is impossible for this graph.

__global__ void probe_kernel(const int* __restrict__ ei32, int E) {
    __shared__ int any_nonzero;
    if (threadIdx.x == 0) any_nonzero = 0;
    __syncthreads();
    int samples = 1024;
    // odd 32-bit words within the first min(2E, 2*samples*2) ints
    for (int i = threadIdx.x; i < samples; i += blockDim.x) {
        int idx = 2 * i + 1;           // odd word
        if (idx < 2 * E && ei32[idx] != 0) atomicOr(&any_nonzero, 1);
    }
    __syncthreads();
    if (threadIdx.x == 0) g_is64 = (any_nonzero == 0) ? 1 : 0;
}

// ---------------- prep ----------------

__global__ void zero_deg_kernel(int n) {
    int i = blockIdx.x * blockDim.x + threadIdx.x;
    if (i < n) g_deg[i] = 0.0f;
}

__device__ __forceinline__ int load_edge_idx(const void* ei, size_t pos) {
    if (g_is64) return (int)((const long long*)ei)[pos];
    return ((const int*)ei)[pos];
}

__global__ void deg_kernel(const void* __restrict__ ei, const float* __restrict__ ew,
                           int E, int n) {
    int e = blockIdx.x * blockDim.x + threadIdx.x;
    if (e < E) {
        int d = load_edge_idx(ei, (size_t)E + e);   // dst row
        if ((unsigned)d < (unsigned)n)
            atomicAdd(&g_deg[d], ew[e]);
    }
}

__global__ void dinv_kernel(int n) {
    int i = blockIdx.x * blockDim.x + threadIdx.x;
    if (i < n) g_dinv[i] = rsqrtf(g_deg[i] + 1.0f);  // +1 self loop; always > 0
}

__global__ void norm_kernel(const void* __restrict__ ei, const float* __restrict__ ew,
                            int E, int n) {
    int e = blockIdx.x * blockDim.x + threadIdx.x;
    if (e < E) {
        int s = load_edge_idx(ei, e);
        int d = load_edge_idx(ei, (size_t)E + e);
        bool ok = (unsigned)s < (unsigned)n && (unsigned)d < (unsigned)n;
        g_src[e] = ok ? s : 0;
        g_dst[e] = ok ? d : 0;
        g_norm[e] = ok ? g_dinv[s] * ew[e] * g_dinv[d] : 0.0f;
    }
}

// ---------------- GEMM: g_h[n,128] = A[n,128] @ W[128,128] (scalar) ----------

__global__ __launch_bounds__(512) void gemm128_kernel(
    const float* __restrict__ A_ext, const float* __restrict__ W,
    int n, int from_gb)
{
    __shared__ float As[64][33];
    __shared__ float Ws[32][128];

    const float* A = from_gb ? (const float*)g_b : A_ext;

    int t = threadIdx.x;
    int row0 = blockIdx.x * 64;
    int tx = t & 31;
    int ty = t >> 5;

    float acc[4][4];
#pragma unroll
    for (int i = 0; i < 4; i++)
#pragma unroll
        for (int j = 0; j < 4; j++) acc[i][j] = 0.0f;

    for (int k0 = 0; k0 < 128; k0 += 32) {
#pragma unroll
        for (int i = 0; i < 4; i++) {
            int idx = t + i * 512;
            int r = idx >> 5;
            int c = idx & 31;
            int grow = row0 + r;
            As[r][c] = (grow < n) ? A[(size_t)grow * 128 + k0 + c] : 0.0f;
        }
#pragma unroll
        for (int i = 0; i < 8; i++) {
            int idx = t + i * 512;
            int kk = idx >> 7;
            int c = idx & 127;
            Ws[kk][c] = W[(size_t)(k0 + kk) * 128 + c];
        }
        __syncthreads();

#pragma unroll
        for (int kk = 0; kk < 32; kk++) {
            float w0 = Ws[kk][tx * 4 + 0];
            float w1 = Ws[kk][tx * 4 + 1];
            float w2 = Ws[kk][tx * 4 + 2];
            float w3 = Ws[kk][tx * 4 + 3];
#pragma unroll
            for (int i = 0; i < 4; i++) {
                float a = As[ty * 4 + i][kk];
                acc[i][0] += a * w0;
                acc[i][1] += a * w1;
                acc[i][2] += a * w2;
                acc[i][3] += a * w3;
            }
        }
        __syncthreads();
    }

#pragma unroll
    for (int i = 0; i < 4; i++) {
        int grow = row0 + ty * 4 + i;
        if (grow < n) {
#pragma unroll
            for (int j = 0; j < 4; j++)
                g_h[(size_t)grow * 128 + tx * 4 + j] = acc[i][j];
        }
    }
}

// ---------------- init: out = g_h*dinv^2 + bias ----------------

__global__ void init_out_kernel(const float* __restrict__ bias,
                                float* __restrict__ out_ext, int n, int to_gb) {
    float* out = to_gb ? (float*)g_b : out_ext;
    int i = blockIdx.x * blockDim.x + threadIdx.x;
    if (i >= n * 128) return;
    int node = i >> 7;
    int f = i & 127;
    float s = g_dinv[node];
    out[i] = g_h[i] * (s * s) + bias[f];
}

// ---------------- scatter: out[dst] += norm * g_h[src]; warp/edge ----------------

__global__ void scatter_kernel(float* __restrict__ out_ext, int E, int to_gb) {
    float* out = to_gb ? (float*)g_b : out_ext;
    int t = blockIdx.x * blockDim.x + threadIdx.x;
    int e = t >> 5;
    int lane = t & 31;
    if (e >= E) return;
    int s = g_src[e];
    int d = g_dst[e];
    float nm = g_norm[e];
    const float* hp = g_h + (size_t)s * 128 + lane * 4;
    float* op = out + (size_t)d * 128 + lane * 4;
    atomicAdd(op + 0, hp[0] * nm);
    atomicAdd(op + 1, hp[1] * nm);
    atomicAdd(op + 2, hp[2] * nm);
    atomicAdd(op + 3, hp[3] * nm);
}

// ---------------- relu on g_b ----------------

__global__ void relu_kernel(int total) {
    int i = blockIdx.x * blockDim.x + threadIdx.x;
    if (i < total) g_b[i] = fmaxf(g_b[i], 0.0f);
}

// ---------------- launch ----------------

extern "C" void kernel_launch(void* const* d_in, const int* in_sizes, int n_in,
                              void* d_out, int out_size) {
    const float* x  = (const float*)d_in[0];
    const void*  ei = d_in[1];                  // int64 or int32 — probed on device
    const float* ew = (const float*)d_in[2];
    const float* W1 = (const float*)d_in[3];
    const float* b1 = (const float*)d_in[4];
    const float* W2 = (const float*)d_in[5];
    const float* b2 = (const float*)d_in[6];
    float*       out = (float*)d_out;

    int n = in_sizes[0] / 128;   // 50000
    int E = in_sizes[2];         // 600000

    const int B = 256;

    probe_kernel<<<1, 256>>>((const int*)ei, E);

    zero_deg_kernel<<<(n + B - 1) / B, B>>>(n);
    deg_kernel<<<(E + B - 1) / B, B>>>(ei, ew, E, n);
    dinv_kernel<<<(n + B - 1) / B, B>>>(n);
    norm_kernel<<<(E + B - 1) / B, B>>>(ei, ew, E, n);

    int gemm_blocks = (n + 63) / 64;
    int total = n * 128;
    int elem_blocks = (total + B - 1) / B;
    long long scat_threads = (long long)E * 32;
    int scat_blocks = (int)((scat_threads + B - 1) / B);

    // layer 1: h = x@W1 ; g_b = agg(h) + b1 ; relu
    gemm128_kernel<<<gemm_blocks, 512>>>(x, W1, n, 0);
    init_out_kernel<<<elem_blocks, B>>>(b1, out, n, 1);
    scatter_kernel<<<scat_blocks, B>>>(out, E, 1);
    relu_kernel<<<elem_blocks, B>>>(total);

    // layer 2: h = g_b@W2 ; out = agg(h) + b2
    gemm128_kernel<<<gemm_blocks, 512>>>(x, W2, n, 1);
    init_out_kernel<<<elem_blocks, B>>>(b2, out, n, 0);
    scatter_kernel<<<scat_blocks, B>>>(out, E, 0);
}

// round 10
// speedup vs baseline: 1.8471x; 1.8471x over previous
#include <cuda_runtime.h>

#define NN 50000
#define DH 128
#define EMAX 600000

__device__ __align__(16) float g_h[(size_t)NN * DH];   // h = A @ W
__device__ __align__(16) float g_b[(size_t)NN * DH];   // layer-1 aggregate / relu'd layer-2 input
__device__ __align__(16) float g_deg[NN];
__device__ __align__(16) float g_dinv[NN];
__device__ __align__(16) float g_norm[EMAX];
__device__ __align__(16) int   g_src[EMAX];
__device__ __align__(16) int   g_dst[EMAX];
__device__ int g_is64;   // 1 if edge_index buffer is int64, 0 if int32

// ---------------- dtype probe ----------------

__global__ void probe_kernel(const int* __restrict__ ei32, int E) {
    __shared__ int any_nonzero;
    if (threadIdx.x == 0) any_nonzero = 0;
    __syncthreads();
    int samples = 1024;
    for (int i = threadIdx.x; i < samples; i += blockDim.x) {
        int idx = 2 * i + 1;           // odd 32-bit word
        if (idx < 2 * E && ei32[idx] != 0) atomicOr(&any_nonzero, 1);
    }
    __syncthreads();
    if (threadIdx.x == 0) g_is64 = (any_nonzero == 0) ? 1 : 0;
}

// ---------------- prep ----------------

__global__ void zero_deg_kernel(int n) {
    int i = blockIdx.x * blockDim.x + threadIdx.x;
    if (i < n) g_deg[i] = 0.0f;
}

__device__ __forceinline__ int load_edge_idx(const void* ei, size_t pos) {
    if (g_is64) return (int)((const long long*)ei)[pos];
    return ((const int*)ei)[pos];
}

__global__ void deg_kernel(const void* __restrict__ ei, const float* __restrict__ ew,
                           int E, int n) {
    int e = blockIdx.x * blockDim.x + threadIdx.x;
    if (e < E) {
        int d = load_edge_idx(ei, (size_t)E + e);
        if ((unsigned)d < (unsigned)n)
            atomicAdd(&g_deg[d], ew[e]);
    }
}

__global__ void dinv_kernel(int n) {
    int i = blockIdx.x * blockDim.x + threadIdx.x;
    if (i < n) g_dinv[i] = rsqrtf(g_deg[i] + 1.0f);
}

__global__ void norm_kernel(const void* __restrict__ ei, const float* __restrict__ ew,
                            int E, int n) {
    int e = blockIdx.x * blockDim.x + threadIdx.x;
    if (e < E) {
        int s = load_edge_idx(ei, e);
        int d = load_edge_idx(ei, (size_t)E + e);
        bool ok = (unsigned)s < (unsigned)n && (unsigned)d < (unsigned)n;
        g_src[e] = ok ? s : 0;
        g_dst[e] = ok ? d : 0;
        g_norm[e] = ok ? g_dinv[s] * ew[e] * g_dinv[d] : 0.0f;
    }
}

// ---------------- GEMM: g_h[n,128] = A[n,128] @ W[128,128] (float4) ----------
// 512 threads/block, 64 rows/block, thread tile 4 rows x 4 cols.

__global__ __launch_bounds__(512) void gemm128_kernel(
    const float* __restrict__ A_ext, const float* __restrict__ W,
    int n, int from_gb)
{
    __shared__ float As[64][32];
    __shared__ float Ws[32][128];

    const float* A = from_gb ? (const float*)g_b : A_ext;

    int t = threadIdx.x;
    int row0 = blockIdx.x * 64;
    int tx = t & 31;
    int ty = t >> 5;

    float4 acc[4];
#pragma unroll
    for (int i = 0; i < 4; i++) acc[i] = make_float4(0.f, 0.f, 0.f, 0.f);

    for (int k0 = 0; k0 < 128; k0 += 32) {
        {
            int r  = t >> 3;   // 0..63
            int cg = t & 7;    // 0..7
            int grow = row0 + r;
            float4 v = make_float4(0.f, 0.f, 0.f, 0.f);
            if (grow < n)
                v = *(const float4*)(A + (size_t)grow * 128 + k0 + cg * 4);
            *(float4*)(&As[r][cg * 4]) = v;
        }
#pragma unroll
        for (int i = 0; i < 2; i++) {
            int idx = t + i * 512;
            int kk = idx >> 5;
            int cg = idx & 31;
            *(float4*)(&Ws[kk][cg * 4]) =
                *(const float4*)(W + (size_t)(k0 + kk) * 128 + cg * 4);
        }
        __syncthreads();

#pragma unroll
        for (int kk = 0; kk < 32; kk++) {
            float4 w = *(float4*)(&Ws[kk][tx * 4]);
#pragma unroll
            for (int i = 0; i < 4; i++) {
                float a = As[ty * 4 + i][kk];   // warp-uniform -> LDS broadcast
                acc[i].x += a * w.x;
                acc[i].y += a * w.y;
                acc[i].z += a * w.z;
                acc[i].w += a * w.w;
            }
        }
        __syncthreads();
    }

#pragma unroll
    for (int i = 0; i < 4; i++) {
        int grow = row0 + ty * 4 + i;
        if (grow < n)
            *(float4*)(g_h + (size_t)grow * 128 + tx * 4) = acc[i];
    }
}

// ---------------- init: out = g_h*dinv^2 + bias (float4) ----------------

__global__ void init_out_kernel(const float* __restrict__ bias,
                                float* __restrict__ out_ext, int n, int to_gb) {
    float* out = to_gb ? (float*)g_b : out_ext;
    int i4 = blockIdx.x * blockDim.x + threadIdx.x;   // float4 index over n*32
    if (i4 >= n * 32) return;
    int node = i4 >> 5;
    int cg = i4 & 31;
    float s = g_dinv[node];
    s = s * s;
    float4 hv = *(const float4*)(g_h + (size_t)i4 * 4);
    float4 bv = *(const float4*)(bias + cg * 4);
    float4 o;
    o.x = hv.x * s + bv.x;
    o.y = hv.y * s + bv.y;
    o.z = hv.z * s + bv.z;
    o.w = hv.w * s + bv.w;
    *(float4*)(out + (size_t)i4 * 4) = o;
}

// ---------------- scatter: out[dst] += norm * g_h[src]; warp/edge, red.v4 ------

__global__ void scatter_kernel(float* __restrict__ out_ext, int E, int to_gb) {
    float* out = to_gb ? (float*)g_b : out_ext;
    int t = blockIdx.x * blockDim.x + threadIdx.x;
    int e = t >> 5;
    int lane = t & 31;
    if (e >= E) return;
    int s = g_src[e];
    int d = g_dst[e];
    float nm = g_norm[e];
    float4 v = *((const float4*)(g_h + (size_t)s * 128) + lane);
    v.x *= nm; v.y *= nm; v.z *= nm; v.w *= nm;
    float* op = out + (size_t)d * 128 + lane * 4;
    asm volatile("red.global.add.v4.f32 [%0], {%1, %2, %3, %4};"
                 :: "l"(op), "f"(v.x), "f"(v.y), "f"(v.z), "f"(v.w)
                 : "memory");
}

// ---------------- relu on g_b (float4) ----------------

__global__ void relu_kernel(int n4) {
    int i = blockIdx.x * blockDim.x + threadIdx.x;
    if (i >= n4) return;
    float4 v = *(float4*)(g_b + (size_t)i * 4);
    v.x = fmaxf(v.x, 0.f);
    v.y = fmaxf(v.y, 0.f);
    v.z = fmaxf(v.z, 0.f);
    v.w = fmaxf(v.w, 0.f);
    *(float4*)(g_b + (size_t)i * 4) = v;
}

// ---------------- launch ----------------

extern "C" void kernel_launch(void* const* d_in, const int* in_sizes, int n_in,
                              void* d_out, int out_size) {
    const float* x  = (const float*)d_in[0];
    const void*  ei = d_in[1];
    const float* ew = (const float*)d_in[2];
    const float* W1 = (const float*)d_in[3];
    const float* b1 = (const float*)d_in[4];
    const float* W2 = (const float*)d_in[5];
    const float* b2 = (const float*)d_in[6];
    float*       out = (float*)d_out;

    int n = in_sizes[0] / 128;   // 50000
    int E = in_sizes[2];         // 600000

    const int B = 256;

    probe_kernel<<<1, 256>>>((const int*)ei, E);

    zero_deg_kernel<<<(n + B - 1) / B, B>>>(n);
    deg_kernel<<<(E + B - 1) / B, B>>>(ei, ew, E, n);
    dinv_kernel<<<(n + B - 1) / B, B>>>(n);
    norm_kernel<<<(E + B - 1) / B, B>>>(ei, ew, E, n);

    int gemm_blocks = (n + 63) / 64;
    int n4 = n * 32;
    int init_blocks = (n4 + B - 1) / B;
    long long scat_threads = (long long)E * 32;
    int scat_blocks = (int)((scat_threads + B - 1) / B);

    // layer 1: h = x@W1 ; g_b = agg(h) + b1 ; relu
    gemm128_kernel<<<gemm_blocks, 512>>>(x, W1, n, 0);
    init_out_kernel<<<init_blocks, B>>>(b1, out, n, 1);
    scatter_kernel<<<scat_blocks, B>>>(out, E, 1);
    relu_kernel<<<init_blocks, B>>>(n4);

    // layer 2: h = g_b@W2 ; out = agg(h) + b2
    gemm128_kernel<<<gemm_blocks, 512>>>(x, W2, n, 1);
    init_out_kernel<<<init_blocks, B>>>(b2, out, n, 0);
    scatter_kernel<<<scat_blocks, B>>>(out, E, 0);
}

// round 12
// speedup vs baseline: 1.9026x; 1.0301x over previous
#include <cuda_runtime.h>

#define NN 50000
#define DH 128
#define EMAX 600000

__device__ __align__(16) float g_h[(size_t)NN * DH];   // h = A @ W
__device__ __align__(16) float g_b[(size_t)NN * DH];   // layer-1 activation
__device__ __align__(16) float g_deg[NN];
__device__ __align__(16) float g_dinv[NN];
__device__ __align__(16) int   g_cnt[NN];          // in-degree histogram
__device__ __align__(16) int   g_rowstart[NN + 1]; // CSR row offsets (by dst)
__device__ __align__(16) int   g_fill[NN];         // insertion cursors
__device__ __align__(16) int   g_csr_src[EMAX];
__device__ __align__(16) float g_csr_norm[EMAX];
__device__ int g_is64;

// ---------------- dtype probe ----------------

__global__ void probe_kernel(const int* __restrict__ ei32, int E) {
    __shared__ int any_nonzero;
    if (threadIdx.x == 0) any_nonzero = 0;
    __syncthreads();
    for (int i = threadIdx.x; i < 1024; i += blockDim.x) {
        int idx = 2 * i + 1;
        if (idx < 2 * E && ei32[idx] != 0) atomicOr(&any_nonzero, 1);
    }
    __syncthreads();
    if (threadIdx.x == 0) g_is64 = (any_nonzero == 0) ? 1 : 0;
}

// ---------------- prep ----------------

__global__ void zero_kernel(int n) {
    int i = blockIdx.x * blockDim.x + threadIdx.x;
    if (i < n) { g_deg[i] = 0.0f; g_cnt[i] = 0; }
}

__device__ __forceinline__ int load_edge_idx(const void* ei, size_t pos) {
    if (g_is64) return (int)((const long long*)ei)[pos];
    return ((const int*)ei)[pos];
}

// weighted degree (float) + in-degree count (int), one pass
__global__ void deg_kernel(const void* __restrict__ ei, const float* __restrict__ ew,
                           int E, int n) {
    int e = blockIdx.x * blockDim.x + threadIdx.x;
    if (e < E) {
        int d = load_edge_idx(ei, (size_t)E + e);
        if ((unsigned)d < (unsigned)n) {
            atomicAdd(&g_deg[d], ew[e]);
            atomicAdd(&g_cnt[d], 1);
        }
    }
}

__global__ void dinv_kernel(int n) {
    int i = blockIdx.x * blockDim.x + threadIdx.x;
    if (i < n) g_dinv[i] = rsqrtf(g_deg[i] + 1.0f);
}

// single-block exclusive scan over g_cnt -> g_rowstart, g_fill
__global__ __launch_bounds__(1024) void scan_kernel(int n) {
    __shared__ int partial[1024];
    int t = threadIdx.x;
    int ch = (n + 1023) / 1024;
    int start = t * ch;
    int sum = 0;
    for (int i = 0; i < ch; i++) {
        int idx = start + i;
        if (idx < n) sum += g_cnt[idx];
    }
    partial[t] = sum;
    __syncthreads();
    // Hillis-Steele inclusive scan
    for (int off = 1; off < 1024; off <<= 1) {
        int v = (t >= off) ? partial[t - off] : 0;
        __syncthreads();
        partial[t] += v;
        __syncthreads();
    }
    int run = (t > 0) ? partial[t - 1] : 0;   // exclusive base for this chunk
    for (int i = 0; i < ch; i++) {
        int idx = start + i;
        if (idx < n) {
            g_rowstart[idx] = run;
            g_fill[idx] = run;
            run += g_cnt[idx];
        }
    }
    if (t == 1023) g_rowstart[n] = partial[1023];
}

// place (src, norm) into CSR buckets by dst
__global__ void build_csr_kernel(const void* __restrict__ ei, const float* __restrict__ ew,
                                 int E, int n) {
    int e = blockIdx.x * blockDim.x + threadIdx.x;
    if (e < E) {
        int s = load_edge_idx(ei, e);
        int d = load_edge_idx(ei, (size_t)E + e);
        if ((unsigned)s < (unsigned)n && (unsigned)d < (unsigned)n) {
            int pos = atomicAdd(&g_fill[d], 1);
            g_csr_src[pos] = s;
            g_csr_norm[pos] = g_dinv[s] * ew[e] * g_dinv[d];
        }
    }
}

// ---------------- GEMM: g_h[n,128] = A[n,128] @ W[128,128] (float4) ----------

__global__ __launch_bounds__(512) void gemm128_kernel(
    const float* __restrict__ A_ext, const float* __restrict__ W,
    int n, int from_gb)
{
    __shared__ float As[64][32];
    __shared__ float Ws[32][128];

    const float* A = from_gb ? (const float*)g_b : A_ext;

    int t = threadIdx.x;
    int row0 = blockIdx.x * 64;
    int tx = t & 31;
    int ty = t >> 5;

    float4 acc[4];
#pragma unroll
    for (int i = 0; i < 4; i++) acc[i] = make_float4(0.f, 0.f, 0.f, 0.f);

    for (int k0 = 0; k0 < 128; k0 += 32) {
        {
            int r  = t >> 3;
            int cg = t & 7;
            int grow = row0 + r;
            float4 v = make_float4(0.f, 0.f, 0.f, 0.f);
            if (grow < n)
                v = *(const float4*)(A + (size_t)grow * 128 + k0 + cg * 4);
            *(float4*)(&As[r][cg * 4]) = v;
        }
#pragma unroll
        for (int i = 0; i < 2; i++) {
            int idx = t + i * 512;
            int kk = idx >> 5;
            int cg = idx & 31;
            *(float4*)(&Ws[kk][cg * 4]) =
                *(const float4*)(W + (size_t)(k0 + kk) * 128 + cg * 4);
        }
        __syncthreads();

#pragma unroll
        for (int kk = 0; kk < 32; kk++) {
            float4 w = *(float4*)(&Ws[kk][tx * 4]);
#pragma unroll
            for (int i = 0; i < 4; i++) {
                float a = As[ty * 4 + i][kk];
                acc[i].x += a * w.x;
                acc[i].y += a * w.y;
                acc[i].z += a * w.z;
                acc[i].w += a * w.w;
            }
        }
        __syncthreads();
    }

#pragma unroll
    for (int i = 0; i < 4; i++) {
        int grow = row0 + ty * 4 + i;
        if (grow < n)
            *(float4*)(g_h + (size_t)grow * 128 + tx * 4) = acc[i];
    }
}

// ---------------- aggregate: warp per dst node, register accumulation ----------
// out[i] = sum_{e in CSR[i]} norm_e * h[src_e] + h[i]*dinv[i]^2 + bias  (opt relu)

__global__ __launch_bounds__(256) void agg_kernel(
    const float* __restrict__ bias, float* __restrict__ out_ext,
    int n, int to_gb, int do_relu)
{
    float* out = to_gb ? (float*)g_b : out_ext;
    int warp = (blockIdx.x * blockDim.x + threadIdx.x) >> 5;
    int lane = threadIdx.x & 31;
    if (warp >= n) return;

    float di = g_dinv[warp];
    float sl = di * di;
    float4 hv = *((const float4*)(g_h + (size_t)warp * 128) + lane);
    float4 bv = *((const float4*)bias + lane);
    float4 acc;
    acc.x = hv.x * sl + bv.x;
    acc.y = hv.y * sl + bv.y;
    acc.z = hv.z * sl + bv.z;
    acc.w = hv.w * sl + bv.w;

    int p  = g_rowstart[warp];
    int p1 = g_rowstart[warp + 1];

    // unroll by 4: batch the index/norm loads, then the 4 gathers (MLP=4)
    for (; p + 3 < p1; p += 4) {
        int   s0 = g_csr_src[p],     s1 = g_csr_src[p + 1];
        int   s2 = g_csr_src[p + 2], s3 = g_csr_src[p + 3];
        float n0 = g_csr_norm[p],     n1 = g_csr_norm[p + 1];
        float n2 = g_csr_norm[p + 2], n3 = g_csr_norm[p + 3];
        float4 v0 = *((const float4*)(g_h + (size_t)s0 * 128) + lane);
        float4 v1 = *((const float4*)(g_h + (size_t)s1 * 128) + lane);
        float4 v2 = *((const float4*)(g_h + (size_t)s2 * 128) + lane);
        float4 v3 = *((const float4*)(g_h + (size_t)s3 * 128) + lane);
        acc.x += n0 * v0.x + n1 * v1.x + n2 * v2.x + n3 * v3.x;
        acc.y += n0 * v0.y + n1 * v1.y + n2 * v2.y + n3 * v3.y;
        acc.z += n0 * v0.z + n1 * v1.z + n2 * v2.z + n3 * v3.z;
        acc.w += n0 * v0.w + n1 * v1.w + n2 * v2.w + n3 * v3.w;
    }
    for (; p < p1; p++) {
        int   sa = g_csr_src[p];
        float na = g_csr_norm[p];
        float4 va = *((const float4*)(g_h + (size_t)sa * 128) + lane);
        acc.x += na * va.x;
        acc.y += na * va.y;
        acc.z += na * va.z;
        acc.w += na * va.w;
    }

    if (do_relu) {
        acc.x = fmaxf(acc.x, 0.f);
        acc.y = fmaxf(acc.y, 0.f);
        acc.z = fmaxf(acc.z, 0.f);
        acc.w = fmaxf(acc.w, 0.f);
    }
    *((float4*)(out + (size_t)warp * 128) + lane) = acc;
}

// ---------------- launch ----------------

extern "C" void kernel_launch(void* const* d_in, const int* in_sizes, int n_in,
                              void* d_out, int out_size) {
    const float* x  = (const float*)d_in[0];
    const void*  ei = d_in[1];
    const float* ew = (const float*)d_in[2];
    const float* W1 = (const float*)d_in[3];
    const float* b1 = (const float*)d_in[4];
    const float* W2 = (const float*)d_in[5];
    const float* b2 = (const float*)d_in[6];
    float*       out = (float*)d_out;

    int n = in_sizes[0] / 128;   // 50000
    int E = in_sizes[2];         // 600000

    const int B = 256;

    probe_kernel<<<1, 256>>>((const int*)ei, E);
    zero_kernel<<<(n + B - 1) / B, B>>>(n);
    deg_kernel<<<(E + B - 1) / B, B>>>(ei, ew, E, n);
    dinv_kernel<<<(n + B - 1) / B, B>>>(n);
    scan_kernel<<<1, 1024>>>(n);
    build_csr_kernel<<<(E + B - 1) / B, B>>>(ei, ew, E, n);

    int gemm_blocks = (n + 63) / 64;
    int agg_blocks = (n * 32 + B - 1) / B;   // warp per node, 8 nodes/block

    // layer 1: h = x@W1 ; g_b = relu(agg(h) + b1)
    gemm128_kernel<<<gemm_blocks, 512>>>(x, W1, n, 0);
    agg_kernel<<<agg_blocks, B>>>(b1, out, n, 1, 1);

    // layer 2: h = g_b@W2 ; out = agg(h) + b2
    gemm128_kernel<<<gemm_blocks, 512>>>(x, W2, n, 1);
    agg_kernel<<<agg_blocks, B>>>(b2, out, n, 0, 0);
}